// round 16
// baseline (speedup 1.0000x reference)
#include <cuda_runtime.h>
#include <cuda_fp16.h>
#include <cstdint>

// Problem constants
#define B_      16
#define QLEN    1024
#define CDIM    1280
#define LLEN    477
#define CROSSD  2048
#define NTOK    200
#define HEADS   20
#define HD      64
#define EHS_LEN 77           // 477 - 200 - 200
#define ATTN_SCALE 0.125f    // 1/sqrt(64)

// ---------------- scratch (device globals; no runtime allocation) ----------
__device__ __half h_q [B_*QLEN*CDIM];
__device__ __half h_k [B_*EHS_LEN*CDIM];
__device__ __half h_v [B_*EHS_LEN*CDIM];
__device__ __half h_bk[B_*NTOK*CDIM];
__device__ __half h_bv[B_*NTOK*CDIM];
__device__ __half h_ck[B_*NTOK*CDIM];
__device__ __half h_cv[B_*NTOK*CDIM];

__device__ __half a_hid[B_*QLEN*CDIM];
__device__ __half a_enc[B_*LLEN*CROSSD];
__device__ __half a_po [B_*QLEN*CDIM];
__device__ __half w_q_h [CDIM*CDIM];
__device__ __half w_k_h [CDIM*CROSSD];
__device__ __half w_v_h [CDIM*CROSSD];
__device__ __half w_kb_h[CDIM*CROSSD];
__device__ __half w_vb_h[CDIM*CROSSD];
__device__ __half w_kc_h[CDIM*CROSSD];
__device__ __half w_vc_h[CDIM*CROSSD];
__device__ __half w_o_h [CDIM*CDIM];

// ---------------- helpers ---------------------------------------------------
__device__ __forceinline__ uint32_t smem_u32(const void* p) {
    uint32_t a;
    asm("{ .reg .u64 t; cvta.to.shared.u64 t, %1; cvt.u32.u64 %0, t; }"
        : "=r"(a) : "l"(p));
    return a;
}

__device__ __forceinline__ void cp_async16(uint32_t dst, const void* src, int pred) {
    int sz = pred ? 16 : 0;
    asm volatile("cp.async.cg.shared.global [%0], [%1], 16, %2;"
                 :: "r"(dst), "l"(src), "r"(sz) : "memory");
}
__device__ __forceinline__ void cp_commit() {
    asm volatile("cp.async.commit_group;" ::: "memory");
}
template <int N>
__device__ __forceinline__ void cp_wait() {
    asm volatile("cp.async.wait_group %0;" :: "n"(N) : "memory");
}

__device__ __forceinline__ void ldm4(uint32_t& r0, uint32_t& r1, uint32_t& r2,
                                     uint32_t& r3, uint32_t addr) {
    asm volatile("ldmatrix.sync.aligned.m8n8.x4.shared.b16 {%0,%1,%2,%3}, [%4];"
                 : "=r"(r0), "=r"(r1), "=r"(r2), "=r"(r3) : "r"(addr));
}

__device__ __forceinline__ void ldm4t(uint32_t& r0, uint32_t& r1, uint32_t& r2,
                                      uint32_t& r3, uint32_t addr) {
    asm volatile("ldmatrix.sync.aligned.m8n8.x4.trans.shared.b16 {%0,%1,%2,%3}, [%4];"
                 : "=r"(r0), "=r"(r1), "=r"(r2), "=r"(r3) : "r"(addr));
}

__device__ __forceinline__ void mma_h(float* c, const uint32_t* a, const uint32_t* b) {
    asm volatile(
        "mma.sync.aligned.m16n8k16.row.col.f32.f16.f16.f32 "
        "{%0,%1,%2,%3}, {%4,%5,%6,%7}, {%8,%9}, {%0,%1,%2,%3};"
        : "+f"(c[0]), "+f"(c[1]), "+f"(c[2]), "+f"(c[3])
        : "r"(a[0]), "r"(a[1]), "r"(a[2]), "r"(a[3]), "r"(b[0]), "r"(b[1]));
}

__device__ __forceinline__ uint32_t pack_h(float a, float b) {
    uint32_t lo = (uint32_t)__half_as_ushort(__float2half_rn(a));
    uint32_t hi = (uint32_t)__half_as_ushort(__float2half_rn(b));
    return lo | (hi << 16);
}

// ---------------- merged conversion kernel ----------------------------------
struct CDesc { const float4* x; __half2* h; int n4; };
struct CPack7 { CDesc d[7]; };

__global__ void cvt_multi(CPack7 p)
{
    CDesc d = p.d[blockIdx.z];
    const int stride = gridDim.x * blockDim.x;
    for (int i = blockIdx.x * blockDim.x + threadIdx.x; i < d.n4; i += stride) {
        float4 v = d.x[i];
        d.h[2*i]   = __floats2half2_rn(v.x, v.y);
        d.h[2*i+1] = __floats2half2_rn(v.z, v.w);
    }
}

// ---------------- fp16 tensor-core GEMM, 128x256 tiles ----------------------
#define KCH 32
#define GSTAGE 24576u
#define GEMM_SMEM (3u * GSTAGE)

struct GDesc {
    const __half* A;
    const __half* W;
    const float*  bias;
    void* C;
    int Mtot, RB;
    long long sA, sC;
    int N, K;
};
struct GPack {
    GDesc d[6];
    int start[7];
};

template <bool HALF_OUT>
__device__ __forceinline__ void gemm_core(const GDesc& g, int m0, int n0)
{
    extern __shared__ char smem[];
    const uint32_t sm = smem_u32(smem);

    const int t    = threadIdx.x;
    const int lane = t & 31;
    const int wid  = t >> 5;
    const int wm   = wid & 1;
    const int wn   = wid >> 1;

    float acc[2][4][4][4];
    #pragma unroll
    for (int w = 0; w < 2; ++w)
        #pragma unroll
        for (int i = 0; i < 4; ++i)
            #pragma unroll
            for (int j = 0; j < 4; ++j)
                #pragma unroll
                for (int k = 0; k < 4; ++k) acc[w][i][j][k] = 0.f;

    const int NC = g.K / KCH;

    auto issue = [&](int c) {
        const int k0 = c * KCH;
        const uint32_t sbase = sm + (uint32_t)(c % 3) * GSTAGE;
        #pragma unroll
        for (int i = 0; i < 2; ++i) {
            int task = t + i * 256;
            int gr   = task >> 2;
            int kc   = task & 3;
            uint32_t sw  = (uint32_t)(kc ^ ((gr >> 1) & 3));
            uint32_t dst = sbase + (uint32_t)gr * 64u + sw * 16u;
            int grow = m0 + gr;
            int pred = grow < g.Mtot;
            long long off = 0;
            if (pred) {
                int b = grow / g.RB, r = grow % g.RB;
                off = (long long)b * g.sA + (long long)r * g.K + k0 + kc * 8;
            }
            cp_async16(dst, g.A + off, pred);
            long long boff0 = (long long)(n0 + gr) * g.K + k0 + kc * 8;
            long long boff1 = (long long)(n0 + 128 + gr) * g.K + k0 + kc * 8;
            cp_async16(dst + 8192u,  g.W + boff0, 1);
            cp_async16(dst + 16384u, g.W + boff1, 1);
        }
        cp_commit();
    };

    auto compute = [&](int c) {
        const uint32_t sbase = sm + (uint32_t)(c % 3) * GSTAGE;
        #pragma unroll
        for (int ks = 0; ks < 2; ++ks) {
            uint32_t af[16];
            #pragma unroll
            for (int mt = 0; mt < 4; ++mt) {
                int arow = wm * 64 + mt * 16 + (lane & 15);
                int ach  = ks * 2 + (lane >> 4);
                uint32_t addr = sbase + (uint32_t)arow * 64u
                              + (uint32_t)((ach ^ ((arow >> 1) & 3)) * 16);
                ldm4(af[mt*4], af[mt*4+1], af[mt*4+2], af[mt*4+3], addr);
            }
            #pragma unroll
            for (int w = 0; w < 2; ++w) {
                uint32_t bh[8];
                #pragma unroll
                for (int nt2 = 0; nt2 < 2; ++nt2) {
                    int brow = wn * 32 + nt2 * 16 + ((lane >> 4) & 1) * 8 + (lane & 7);
                    int bch  = ks * 2 + ((lane >> 3) & 1);
                    uint32_t addr = sbase + 8192u + (uint32_t)w * 8192u
                                  + (uint32_t)brow * 64u
                                  + (uint32_t)((bch ^ ((brow >> 1) & 3)) * 16);
                    ldm4(bh[nt2*4], bh[nt2*4+1], bh[nt2*4+2], bh[nt2*4+3], addr);
                }
                #pragma unroll
                for (int mt = 0; mt < 4; ++mt)
                    #pragma unroll
                    for (int nt = 0; nt < 4; ++nt)
                        mma_h(acc[w][mt][nt], &af[mt*4], &bh[(nt >> 1)*4 + (nt & 1)*2]);
            }
        }
    };

    issue(0);
    issue(1);
    for (int c = 0; c < NC; ++c) {
        if (c + 1 < NC) { cp_wait<1>(); } else { cp_wait<0>(); }
        __syncthreads();
        compute(c);
        if (c + 2 < NC) issue(c + 2);
    }

    const int gg = lane >> 2;
    const int q4 = lane & 3;
    #pragma unroll
    for (int w = 0; w < 2; ++w) {
        int nbase = n0 + w * 128 + wn * 32;
        #pragma unroll
        for (int mt = 0; mt < 4; ++mt) {
            #pragma unroll
            for (int half = 0; half < 2; ++half) {
                int grow = m0 + wm * 64 + mt * 16 + gg + half * 8;
                if (grow < g.Mtot) {
                    int b = grow / g.RB, r = grow % g.RB;
                    long long rowoff = (long long)b * g.sC + (long long)r * g.N + nbase;
                    #pragma unroll
                    for (int nt = 0; nt < 4; ++nt) {
                        int ncol = nt * 8 + q4 * 2;
                        float vx = acc[w][mt][nt][half*2+0];
                        float vy = acc[w][mt][nt][half*2+1];
                        if (HALF_OUT) {
                            __half* crow = (__half*)g.C + rowoff;
                            *(__half2*)&crow[ncol] = __floats2half2_rn(vx, vy);
                        } else {
                            float* crow = (float*)g.C + rowoff;
                            float2 v;
                            v.x = vx + (g.bias ? g.bias[nbase + ncol]     : 0.f);
                            v.y = vy + (g.bias ? g.bias[nbase + ncol + 1] : 0.f);
                            *(float2*)&crow[ncol] = v;
                        }
                    }
                }
            }
        }
    }
}

__global__ __launch_bounds__(256)
void gemm_one(GDesc g)
{
    gemm_core<false>(g, blockIdx.y * 128, blockIdx.x * 256);
}

__global__ __launch_bounds__(256)
void gemm_one_h(GDesc g)
{
    gemm_core<true>(g, blockIdx.y * 128, blockIdx.x * 256);
}

__global__ __launch_bounds__(256)
void gemm_pack(GPack p)
{
    const int bx = blockIdx.x;
    int di = 0;
    #pragma unroll
    for (int i = 0; i < 6; ++i)
        if (bx >= p.start[i] && bx < p.start[i+1]) di = i;
    const int local = bx - p.start[di];
    gemm_core<true>(p.d[di], (local / 5) * 128, (local % 5) * 256);
}

// ---------------- Tensor-core attention (pure fp16, kv-major V) -------------
#define PAIR_SMEM  69632u
#define FUSED_SMEM 90112u
#define AQH 0u
#define P_AK 16384u
#define P_AV 43008u
#define F_AKE 16384u
#define F_AVE 26624u
#define F_AKB 36864u
#define F_AVB 63488u

template <bool CHECK>
__device__ __forceinline__ void att_stage_q(char* smc, const __half* Qb,
                                            int Sq, int q0, int t)
{
    #pragma unroll
    for (int i = 0; i < 4; ++i) {
        int lin = t + i * 256;
        int row = lin >> 3;
        int ch  = lin & 7;
        uint4 v = make_uint4(0u, 0u, 0u, 0u);
        if (!CHECK || q0 + row < Sq)
            v = *(const uint4*)&Qb[(long long)(q0 + row) * CDIM + ch * 8];
        uint32_t off = (uint32_t)row * 128u + (uint32_t)((ch ^ (row & 7)) * 16);
        *(uint4*)(smc + AQH + off) = v;
    }
}

__device__ __forceinline__ void att_stage_kv(char* smc, uint32_t koff_base,
                                             uint32_t voff_base,
                                             const __half* Kb, const __half* Vb,
                                             int Skv, int nkv, int t)
{
    for (int lin = t; lin < nkv * 8; lin += 256) {
        int row = lin >> 3;
        int ch  = lin & 7;
        uint4 kv = make_uint4(0u, 0u, 0u, 0u);
        uint4 vv = make_uint4(0u, 0u, 0u, 0u);
        if (row < Skv) {
            kv = *(const uint4*)&Kb[(long long)row * CDIM + ch * 8];
            vv = *(const uint4*)&Vb[(long long)row * CDIM + ch * 8];
        }
        uint32_t off = (uint32_t)row * 128u + (uint32_t)((ch ^ (row & 7)) * 16);
        *(uint4*)(smc + koff_base + off) = kv;
        *(uint4*)(smc + voff_base + off) = vv;
    }
}

template <int SKV>
__device__ __forceinline__ void att_phase(uint32_t sm_q, uint32_t sm_k, uint32_t sm_v,
                                          int lane, int qbase,
                                          float* mrow, float* lrow, float O[8][4])
{
    constexpr int NCH = (SKV + 63) / 64;
    #pragma unroll
    for (int c = 0; c < NCH; ++c) {
        const int REM = SKV - c * 64;
        const int NKT = REM >= 64 ? 4 : (REM + 15) / 16;

        float S[8][4];
        #pragma unroll
        for (int nt = 0; nt < 8; ++nt)
            #pragma unroll
            for (int e = 0; e < 4; ++e) S[nt][e] = 0.f;

        #pragma unroll
        for (int ks = 0; ks < 4; ++ks) {
            uint32_t qh[4], kh[4];
            int arow = qbase + (lane & 15);
            int ach  = 2 * ks + (lane >> 4);
            uint32_t aoff = (uint32_t)arow * 128u + (uint32_t)((ach ^ (arow & 7)) * 16);
            ldm4(qh[0], qh[1], qh[2], qh[3], sm_q + aoff);
            #pragma unroll
            for (int nt2 = 0; nt2 < 4; ++nt2) {
                if (nt2 < NKT) {
                    int brow = c * 64 + nt2 * 16 + ((lane >> 4) & 1) * 8 + (lane & 7);
                    int bch  = 2 * ks + ((lane >> 3) & 1);
                    uint32_t boff = (uint32_t)brow * 128u
                                  + (uint32_t)((bch ^ (brow & 7)) * 16);
                    ldm4(kh[0], kh[1], kh[2], kh[3], sm_k + boff);
                    #pragma unroll
                    for (int sub = 0; sub < 2; ++sub)
                        mma_h(S[nt2 * 2 + sub], qh, &kh[sub*2]);
                }
            }
        }

        #pragma unroll
        for (int nt = 0; nt < 8; ++nt) {
            int col0 = c * 64 + nt * 8 + 2 * (lane & 3);
            #pragma unroll
            for (int e = 0; e < 4; ++e) {
                int col = col0 + (e & 1);
                float v = S[nt][e] * ATTN_SCALE;
                S[nt][e] = (col < SKV) ? v : -1e30f;
            }
        }

        float mx[2] = {-1e30f, -1e30f};
        #pragma unroll
        for (int nt = 0; nt < 8; ++nt) {
            mx[0] = fmaxf(mx[0], fmaxf(S[nt][0], S[nt][1]));
            mx[1] = fmaxf(mx[1], fmaxf(S[nt][2], S[nt][3]));
        }
        #pragma unroll
        for (int off = 1; off <= 2; off <<= 1) {
            mx[0] = fmaxf(mx[0], __shfl_xor_sync(0xffffffffu, mx[0], off));
            mx[1] = fmaxf(mx[1], __shfl_xor_sync(0xffffffffu, mx[1], off));
        }
        float mnew0 = fmaxf(mrow[0], mx[0]);
        float mnew1 = fmaxf(mrow[1], mx[1]);
        float corr0 = __expf(mrow[0] - mnew0);
        float corr1 = __expf(mrow[1] - mnew1);

        float ls[2] = {0.f, 0.f};
        #pragma unroll
        for (int nt = 0; nt < 8; ++nt) {
            S[nt][0] = __expf(S[nt][0] - mnew0); ls[0] += S[nt][0];
            S[nt][1] = __expf(S[nt][1] - mnew0); ls[0] += S[nt][1];
            S[nt][2] = __expf(S[nt][2] - mnew1); ls[1] += S[nt][2];
            S[nt][3] = __expf(S[nt][3] - mnew1); ls[1] += S[nt][3];
        }
        #pragma unroll
        for (int off = 1; off <= 2; off <<= 1) {
            ls[0] += __shfl_xor_sync(0xffffffffu, ls[0], off);
            ls[1] += __shfl_xor_sync(0xffffffffu, ls[1], off);
        }
        lrow[0] = lrow[0] * corr0 + ls[0];
        lrow[1] = lrow[1] * corr1 + ls[1];
        mrow[0] = mnew0; mrow[1] = mnew1;
        #pragma unroll
        for (int nt = 0; nt < 8; ++nt) {
            O[nt][0] *= corr0; O[nt][1] *= corr0;
            O[nt][2] *= corr1; O[nt][3] *= corr1;
        }

        #pragma unroll
        for (int ks = 0; ks < 4; ++ks) {
            if (ks < NKT) {
                uint32_t aph[4];
                {
                    int T0 = 2 * ks, T1 = 2 * ks + 1;
                    aph[0] = pack_h(S[T0][0], S[T0][1]);
                    aph[1] = pack_h(S[T0][2], S[T0][3]);
                    aph[2] = pack_h(S[T1][0], S[T1][1]);
                    aph[3] = pack_h(S[T1][2], S[T1][3]);
                }
                int krow = c * 64 + ks * 16 + (lane & 15);
                #pragma unroll
                for (int nt2 = 0; nt2 < 4; ++nt2) {
                    int chunk = nt2 * 2 + ((lane >> 4) & 1);
                    uint32_t voff = (uint32_t)krow * 128u
                                  + (uint32_t)((chunk ^ (krow & 7)) * 16);
                    uint32_t vh[4];
                    ldm4t(vh[0], vh[1], vh[2], vh[3], sm_v + voff);
                    mma_h(O[nt2 * 2 + 0], aph, &vh[0]);
                    mma_h(O[nt2 * 2 + 1], aph, &vh[2]);
                }
            }
        }
    }
}

__global__ __launch_bounds__(256, 2)
void attn_pair(__half* __restrict__ bk, __half* __restrict__ bv,
               const __half* __restrict__ ck, const __half* __restrict__ cv)
{
    extern __shared__ char smem[];
    char* smc = smem;
    const uint32_t sm = smem_u32(smem);

    const int t  = threadIdx.x;
    const int z  = blockIdx.z;
    const int b  = z >> 1;
    __half* Xg = (z & 1) ? bv : bk;
    const int h  = blockIdx.y;
    const int q0 = blockIdx.x * 128;

    const __half* Qb = Xg + ((long long)b * NTOK) * CDIM + h * HD;
    const __half* Kb = ck + ((long long)b * NTOK) * CDIM + h * HD;
    const __half* Vb = cv + ((long long)b * NTOK) * CDIM + h * HD;
    __half*       Ob = Xg + ((long long)b * NTOK) * CDIM + h * HD;

    att_stage_q<true>(smc, Qb, NTOK, q0, t);
    att_stage_kv(smc, P_AK, P_AV, Kb, Vb, NTOK, 208, t);
    __syncthreads();

    const int lane  = t & 31;
    const int wid   = t >> 5;
    const int qbase = wid * 16;

    if (q0 + qbase >= NTOK) return;

    float O[8][4];
    #pragma unroll
    for (int nt = 0; nt < 8; ++nt)
        #pragma unroll
        for (int e = 0; e < 4; ++e) O[nt][e] = 0.f;
    float mrow[2] = {-1e30f, -1e30f};
    float lrow[2] = {0.f, 0.f};

    att_phase<NTOK>(sm + AQH, sm + P_AK, sm + P_AV, lane, qbase, mrow, lrow, O);

    float inv0 = 1.f / lrow[0];
    float inv1 = 1.f / lrow[1];
    #pragma unroll
    for (int halfq = 0; halfq < 2; ++halfq) {
        int row = q0 + qbase + (lane >> 2) + halfq * 8;
        if (row < NTOK) {
            float inv = halfq ? inv1 : inv0;
            __half* op = Ob + (long long)row * CDIM;
            #pragma unroll
            for (int nt = 0; nt < 8; ++nt) {
                int d = nt * 8 + 2 * (lane & 3);
                __half2 old = *(__half2*)&op[d];
                float ox = __half2float(__low2half(old))  + O[nt][halfq*2+0] * inv;
                float oy = __half2float(__high2half(old)) + O[nt][halfq*2+1] * inv;
                *(__half2*)&op[d] = __floats2half2_rn(ox, oy);
            }
        }
    }
}

__global__ __launch_bounds__(256, 2)
void attn_fused(const __half* __restrict__ Qg, const __half* __restrict__ Kg,
                const __half* __restrict__ Vg, const __half* __restrict__ bKg,
                const __half* __restrict__ bVg, __half* __restrict__ Og)
{
    extern __shared__ char smem[];
    char* smc = smem;
    const uint32_t sm = smem_u32(smem);

    const int t  = threadIdx.x;
    const int b  = blockIdx.z;
    const int h  = blockIdx.y;
    const int q0 = blockIdx.x * 128;

    const __half* Qb  = Qg  + ((long long)b * QLEN)    * CDIM + h * HD;
    const __half* Kb  = Kg  + ((long long)b * EHS_LEN) * CDIM + h * HD;
    const __half* Vb  = Vg  + ((long long)b * EHS_LEN) * CDIM + h * HD;
    const __half* bKb = bKg + ((long long)b * NTOK)    * CDIM + h * HD;
    const __half* bVb = bVg + ((long long)b * NTOK)    * CDIM + h * HD;
    __half*       Ob  = Og  + ((long long)b * QLEN)    * CDIM + h * HD;

    att_stage_q<false>(smc, Qb, QLEN, q0, t);
    att_stage_kv(smc, F_AKE, F_AVE, Kb,  Vb,  EHS_LEN, 80,  t);
    att_stage_kv(smc, F_AKB, F_AVB, bKb, bVb, NTOK,    208, t);
    __syncthreads();

    const int lane  = t & 31;
    const int wid   = t >> 5;
    const int qbase = wid * 16;

    float O[8][4];
    float mrow[2], lrow[2];
    #pragma unroll
    for (int nt = 0; nt < 8; ++nt)
        #pragma unroll
        for (int e = 0; e < 4; ++e) O[nt][e] = 0.f;
    mrow[0] = mrow[1] = -1e30f;
    lrow[0] = lrow[1] = 0.f;

    att_phase<EHS_LEN>(sm + AQH, sm + F_AKE, sm + F_AVE, lane, qbase, mrow, lrow, O);

    float Oacc[8][4];
    {
        float inv0 = 1.f / lrow[0];
        float inv1 = 1.f / lrow[1];
        #pragma unroll
        for (int nt = 0; nt < 8; ++nt) {
            Oacc[nt][0] = O[nt][0] * inv0;
            Oacc[nt][1] = O[nt][1] * inv0;
            Oacc[nt][2] = O[nt][2] * inv1;
            Oacc[nt][3] = O[nt][3] * inv1;
            O[nt][0] = O[nt][1] = O[nt][2] = O[nt][3] = 0.f;
        }
        mrow[0] = mrow[1] = -1e30f;
        lrow[0] = lrow[1] = 0.f;
    }

    att_phase<NTOK>(sm + AQH, sm + F_AKB, sm + F_AVB, lane, qbase, mrow, lrow, O);

    float inv0 = 1.f / lrow[0];
    float inv1 = 1.f / lrow[1];
    #pragma unroll
    for (int halfq = 0; halfq < 2; ++halfq) {
        int row = q0 + qbase + (lane >> 2) + halfq * 8;
        {
            float inv = halfq ? inv1 : inv0;
            __half* op = Ob + (long long)row * CDIM;
            #pragma unroll
            for (int nt = 0; nt < 8; ++nt) {
                int d = nt * 8 + 2 * (lane & 3);
                float vx = Oacc[nt][halfq*2+0] + O[nt][halfq*2+0] * inv;
                float vy = Oacc[nt][halfq*2+1] + O[nt][halfq*2+1] * inv;
                *(__half2*)&op[d] = __floats2half2_rn(vx, vy);
            }
        }
    }
}

// ---------------- host orchestration ---------------------------------------
template <typename T>
static inline T* sym(const void* s) { void* p; cudaGetSymbolAddress(&p, s); return (T*)p; }

extern "C" void kernel_launch(void* const* d_in, const int* in_sizes, int n_in,
                              void* d_out, int out_size)
{
    const float* hidden = (const float*)d_in[0];
    const float* enc    = (const float*)d_in[1];
    const float* w_q    = (const float*)d_in[2];
    const float* w_k    = (const float*)d_in[3];
    const float* w_v    = (const float*)d_in[4];
    const float* w_kb   = (const float*)d_in[5];
    const float* w_vb   = (const float*)d_in[6];
    const float* w_kc   = (const float*)d_in[7];
    const float* w_vc   = (const float*)d_in[8];
    const float* w_out  = (const float*)d_in[9];
    const float* b_out  = (const float*)d_in[10];
    float* out = (float*)d_out;

    __half* pq  = sym<__half>(&h_q);
    __half* pk  = sym<__half>(&h_k);
    __half* pv  = sym<__half>(&h_v);
    __half* pbk = sym<__half>(&h_bk);
    __half* pbv = sym<__half>(&h_bv);
    __half* pck = sym<__half>(&h_ck);
    __half* pcv = sym<__half>(&h_cv);

    __half* hidh = sym<__half>(&a_hid);
    __half* ench = sym<__half>(&a_enc);
    __half* poh  = sym<__half>(&a_po);
    __half* wqh  = sym<__half>(&w_q_h);
    __half* wkh  = sym<__half>(&w_k_h);
    __half* wvh  = sym<__half>(&w_v_h);
    __half* wkbh = sym<__half>(&w_kb_h);
    __half* wvbh = sym<__half>(&w_vb_h);
    __half* wkch = sym<__half>(&w_kc_h);
    __half* wvch = sym<__half>(&w_vc_h);
    __half* woh  = sym<__half>(&w_o_h);

    const long long bsEnc = (long long)LLEN * CROSSD;
    const long long encN  = (long long)B_ * LLEN * CROSSD;
    const long long hidN  = (long long)B_ * QLEN * CDIM;
    const long long boxOff = (long long)EHS_LEN * CROSSD;
    const long long clsOff = (long long)(EHS_LEN + NTOK) * CROSSD;

    // one-time host objects (host-side only; no device allocation)
    static cudaStream_t s1 = nullptr, s2 = nullptr;
    static cudaEvent_t eS = nullptr, eCvt2 = nullptr, eEnc = nullptr, ePair = nullptr;
    if (!s1) {
        cudaStreamCreateWithFlags(&s1, cudaStreamNonBlocking);
        cudaStreamCreateWithFlags(&s2, cudaStreamNonBlocking);
        cudaEventCreateWithFlags(&eS,    cudaEventDisableTiming);
        cudaEventCreateWithFlags(&eCvt2, cudaEventDisableTiming);
        cudaEventCreateWithFlags(&eEnc,  cudaEventDisableTiming);
        cudaEventCreateWithFlags(&ePair, cudaEventDisableTiming);
        cudaFuncSetAttribute(gemm_one,   cudaFuncAttributeMaxDynamicSharedMemorySize, GEMM_SMEM);
        cudaFuncSetAttribute(gemm_one_h, cudaFuncAttributeMaxDynamicSharedMemorySize, GEMM_SMEM);
        cudaFuncSetAttribute(gemm_pack,  cudaFuncAttributeMaxDynamicSharedMemorySize, GEMM_SMEM);
        cudaFuncSetAttribute(attn_pair,  cudaFuncAttributeMaxDynamicSharedMemorySize, PAIR_SMEM);
        cudaFuncSetAttribute(attn_fused, cudaFuncAttributeMaxDynamicSharedMemorySize, FUSED_SMEM);
    }

    // fork point
    cudaEventRecord(eS, 0);
    cudaStreamWaitEvent(s1, eS, 0);

    // s1: conversions for the q-proj / out-proj chain (hidden, w_q, w_out)
    {
        CPack7 cp;
        cp.d[0] = { (const float4*)hidden, (__half2*)hidh, (int)(hidN / 4) };
        cp.d[1] = { (const float4*)w_q,    (__half2*)wqh,  CDIM * CDIM / 4 };
        cp.d[2] = { (const float4*)w_out,  (__half2*)woh,  CDIM * CDIM / 4 };
        dim3 grid(2048, 1, 3);
        cvt_multi<<<grid, 256, 0, s1>>>(cp);
        cudaEventRecord(eCvt2, s1);
    }

    // stream 0: encoder conversions (enc + 6 encoder weights)
    {
        CPack7 cp;
        cp.d[0] = { (const float4*)enc,  (__half2*)ench, (int)(encN / 4) };
        cp.d[1] = { (const float4*)w_k,  (__half2*)wkh,  CDIM * CROSSD / 4 };
        cp.d[2] = { (const float4*)w_v,  (__half2*)wvh,  CDIM * CROSSD / 4 };
        cp.d[3] = { (const float4*)w_kb, (__half2*)wkbh, CDIM * CROSSD / 4 };
        cp.d[4] = { (const float4*)w_vb, (__half2*)wvbh, CDIM * CROSSD / 4 };
        cp.d[5] = { (const float4*)w_kc, (__half2*)wkch, CDIM * CROSSD / 4 };
        cp.d[6] = { (const float4*)w_vc, (__half2*)wvch, CDIM * CROSSD / 4 };
        dim3 grid(2048, 1, 7);
        cvt_multi<<<grid, 256>>>(cp);
    }

    // stream 0: 6 encoder projections (packed)
    {
        GPack p;
        const long long sEk = (long long)EHS_LEN*CDIM;
        const long long sNk = (long long)NTOK*CDIM;
        p.d[0] = { ench,          wkh,  nullptr, pk,  B_*EHS_LEN, EHS_LEN, bsEnc, sEk, CDIM, CROSSD };
        p.d[1] = { ench,          wvh,  nullptr, pv,  B_*EHS_LEN, EHS_LEN, bsEnc, sEk, CDIM, CROSSD };
        p.d[2] = { ench + boxOff, wkbh, nullptr, pbk, B_*NTOK,    NTOK,    bsEnc, sNk, CDIM, CROSSD };
        p.d[3] = { ench + boxOff, wvbh, nullptr, pbv, B_*NTOK,    NTOK,    bsEnc, sNk, CDIM, CROSSD };
        p.d[4] = { ench + clsOff, wkch, nullptr, pck, B_*NTOK,    NTOK,    bsEnc, sNk, CDIM, CROSSD };
        p.d[5] = { ench + clsOff, wvch, nullptr, pcv, B_*NTOK,    NTOK,    bsEnc, sNk, CDIM, CROSSD };
        int acc = 0;
        for (int i = 0; i < 6; ++i) {
            p.start[i] = acc;
            int mt = (p.d[i].Mtot + 127) / 128;
            acc += mt * 5;
        }
        p.start[6] = acc;
        gemm_pack<<<acc, 256, GEMM_SMEM>>>(p);
        cudaEventRecord(eEnc, 0);
    }

    // s2: attn_pair concurrently with q-proj (depends only on encoder projs)
    cudaStreamWaitEvent(s2, eEnc, 0);
    {
        dim3 grid((NTOK + 127) / 128, HEADS, 2 * B_);
        attn_pair<<<grid, 256, PAIR_SMEM, s2>>>(pbk, pbv, pck, pcv);
        cudaEventRecord(ePair, s2);
    }

    // stream 0: q-projection (needs cvt2)
    cudaStreamWaitEvent(0, eCvt2, 0);
    {
        GDesc g = { hidh, wqh, nullptr, pq, B_*QLEN, B_*QLEN, 0, 0, CDIM, CDIM };
        dim3 grid(CDIM / 256, (B_*QLEN + 127) / 128, 1);
        gemm_one_h<<<grid, 256, GEMM_SMEM>>>(g);
    }

    // stream 0: fused main + box attention (needs q-proj + attn_pair)
    cudaStreamWaitEvent(0, ePair, 0);
    {
        dim3 grid(QLEN / 128, HEADS, B_);
        attn_fused<<<grid, 256, FUSED_SMEM>>>(pq, pk, pv, pbk, pbv, poh);
    }

    // stream 0: out-projection (fp32 + bias) into d_out
    {
        GDesc g = { poh, woh, b_out, out, B_*QLEN, B_*QLEN, 0, 0, CDIM, CDIM };
        dim3 grid(CDIM / 256, (B_*QLEN + 127) / 128, 1);
        gemm_one<<<grid, 256, GEMM_SMEM>>>(g);
    }
}

// round 17
// speedup vs baseline: 1.0128x; 1.0128x over previous
#include <cuda_runtime.h>
#include <cuda_fp16.h>
#include <cstdint>

// Problem constants
#define B_      16
#define QLEN    1024
#define CDIM    1280
#define LLEN    477
#define CROSSD  2048
#define NTOK    200
#define HEADS   20
#define HD      64
#define EHS_LEN 77           // 477 - 200 - 200
#define ATTN_SCALE 0.125f    // 1/sqrt(64)

// ---------------- scratch (device globals; no runtime allocation) ----------
__device__ __half h_q [B_*QLEN*CDIM];
__device__ __half h_k [B_*EHS_LEN*CDIM];
__device__ __half h_v [B_*EHS_LEN*CDIM];
__device__ __half h_bk[B_*NTOK*CDIM];
__device__ __half h_bv[B_*NTOK*CDIM];
__device__ __half h_ck[B_*NTOK*CDIM];
__device__ __half h_cv[B_*NTOK*CDIM];

__device__ __half a_hid[B_*QLEN*CDIM];
__device__ __half a_enc[B_*LLEN*CROSSD];
__device__ __half a_po [B_*QLEN*CDIM];
__device__ __half w_q_h [CDIM*CDIM];
__device__ __half w_k_h [CDIM*CROSSD];
__device__ __half w_v_h [CDIM*CROSSD];
__device__ __half w_kb_h[CDIM*CROSSD];
__device__ __half w_vb_h[CDIM*CROSSD];
__device__ __half w_kc_h[CDIM*CROSSD];
__device__ __half w_vc_h[CDIM*CROSSD];
__device__ __half w_o_h [CDIM*CDIM];

// ---------------- helpers ---------------------------------------------------
__device__ __forceinline__ uint32_t smem_u32(const void* p) {
    uint32_t a;
    asm("{ .reg .u64 t; cvta.to.shared.u64 t, %1; cvt.u32.u64 %0, t; }"
        : "=r"(a) : "l"(p));
    return a;
}

__device__ __forceinline__ void cp_async16(uint32_t dst, const void* src, int pred) {
    int sz = pred ? 16 : 0;
    asm volatile("cp.async.cg.shared.global [%0], [%1], 16, %2;"
                 :: "r"(dst), "l"(src), "r"(sz) : "memory");
}
__device__ __forceinline__ void cp_commit() {
    asm volatile("cp.async.commit_group;" ::: "memory");
}
template <int N>
__device__ __forceinline__ void cp_wait() {
    asm volatile("cp.async.wait_group %0;" :: "n"(N) : "memory");
}

__device__ __forceinline__ void ldm4(uint32_t& r0, uint32_t& r1, uint32_t& r2,
                                     uint32_t& r3, uint32_t addr) {
    asm volatile("ldmatrix.sync.aligned.m8n8.x4.shared.b16 {%0,%1,%2,%3}, [%4];"
                 : "=r"(r0), "=r"(r1), "=r"(r2), "=r"(r3) : "r"(addr));
}

__device__ __forceinline__ void ldm4t(uint32_t& r0, uint32_t& r1, uint32_t& r2,
                                      uint32_t& r3, uint32_t addr) {
    asm volatile("ldmatrix.sync.aligned.m8n8.x4.trans.shared.b16 {%0,%1,%2,%3}, [%4];"
                 : "=r"(r0), "=r"(r1), "=r"(r2), "=r"(r3) : "r"(addr));
}

__device__ __forceinline__ void mma_h(float* c, const uint32_t* a, const uint32_t* b) {
    asm volatile(
        "mma.sync.aligned.m16n8k16.row.col.f32.f16.f16.f32 "
        "{%0,%1,%2,%3}, {%4,%5,%6,%7}, {%8,%9}, {%0,%1,%2,%3};"
        : "+f"(c[0]), "+f"(c[1]), "+f"(c[2]), "+f"(c[3])
        : "r"(a[0]), "r"(a[1]), "r"(a[2]), "r"(a[3]), "r"(b[0]), "r"(b[1]));
}

__device__ __forceinline__ uint32_t pack_h(float a, float b) {
    uint32_t lo = (uint32_t)__half_as_ushort(__float2half_rn(a));
    uint32_t hi = (uint32_t)__half_as_ushort(__float2half_rn(b));
    return lo | (hi << 16);
}

// ---------------- merged conversion kernel ----------------------------------
struct CDesc { const float4* x; __half2* h; int n4; };
struct CPack10 { CDesc d[10]; };

__global__ void cvt_multi10(CPack10 p)
{
    CDesc d = p.d[blockIdx.z];
    const int stride = gridDim.x * blockDim.x;
    for (int i = blockIdx.x * blockDim.x + threadIdx.x; i < d.n4; i += stride) {
        float4 v = d.x[i];
        d.h[2*i]   = __floats2half2_rn(v.x, v.y);
        d.h[2*i+1] = __floats2half2_rn(v.z, v.w);
    }
}

// ---------------- fp16 tensor-core GEMM, 128x256 tiles ----------------------
#define KCH 32
#define GSTAGE 24576u
#define GEMM_SMEM (3u * GSTAGE)

struct GDesc {
    const __half* A;
    const __half* W;
    const float*  bias;
    void* C;
    int Mtot, RB;
    long long sA, sC;
    int N, K;
};
struct GPack {
    GDesc d[7];
    int start[8];
};

template <bool HALF_OUT>
__device__ __forceinline__ void gemm_core(const GDesc& g, int m0, int n0)
{
    extern __shared__ char smem[];
    const uint32_t sm = smem_u32(smem);

    const int t    = threadIdx.x;
    const int lane = t & 31;
    const int wid  = t >> 5;
    const int wm   = wid & 1;
    const int wn   = wid >> 1;

    float acc[2][4][4][4];
    #pragma unroll
    for (int w = 0; w < 2; ++w)
        #pragma unroll
        for (int i = 0; i < 4; ++i)
            #pragma unroll
            for (int j = 0; j < 4; ++j)
                #pragma unroll
                for (int k = 0; k < 4; ++k) acc[w][i][j][k] = 0.f;

    const int NC = g.K / KCH;

    auto issue = [&](int c) {
        const int k0 = c * KCH;
        const uint32_t sbase = sm + (uint32_t)(c % 3) * GSTAGE;
        #pragma unroll
        for (int i = 0; i < 2; ++i) {
            int task = t + i * 256;
            int gr   = task >> 2;
            int kc   = task & 3;
            uint32_t sw  = (uint32_t)(kc ^ ((gr >> 1) & 3));
            uint32_t dst = sbase + (uint32_t)gr * 64u + sw * 16u;
            int grow = m0 + gr;
            int pred = grow < g.Mtot;
            long long off = 0;
            if (pred) {
                int b = grow / g.RB, r = grow % g.RB;
                off = (long long)b * g.sA + (long long)r * g.K + k0 + kc * 8;
            }
            cp_async16(dst, g.A + off, pred);
            long long boff0 = (long long)(n0 + gr) * g.K + k0 + kc * 8;
            long long boff1 = (long long)(n0 + 128 + gr) * g.K + k0 + kc * 8;
            cp_async16(dst + 8192u,  g.W + boff0, 1);
            cp_async16(dst + 16384u, g.W + boff1, 1);
        }
        cp_commit();
    };

    auto compute = [&](int c) {
        const uint32_t sbase = sm + (uint32_t)(c % 3) * GSTAGE;
        #pragma unroll
        for (int ks = 0; ks < 2; ++ks) {
            uint32_t af[16];
            #pragma unroll
            for (int mt = 0; mt < 4; ++mt) {
                int arow = wm * 64 + mt * 16 + (lane & 15);
                int ach  = ks * 2 + (lane >> 4);
                uint32_t addr = sbase + (uint32_t)arow * 64u
                              + (uint32_t)((ach ^ ((arow >> 1) & 3)) * 16);
                ldm4(af[mt*4], af[mt*4+1], af[mt*4+2], af[mt*4+3], addr);
            }
            #pragma unroll
            for (int w = 0; w < 2; ++w) {
                uint32_t bh[8];
                #pragma unroll
                for (int nt2 = 0; nt2 < 2; ++nt2) {
                    int brow = wn * 32 + nt2 * 16 + ((lane >> 4) & 1) * 8 + (lane & 7);
                    int bch  = ks * 2 + ((lane >> 3) & 1);
                    uint32_t addr = sbase + 8192u + (uint32_t)w * 8192u
                                  + (uint32_t)brow * 64u
                                  + (uint32_t)((bch ^ ((brow >> 1) & 3)) * 16);
                    ldm4(bh[nt2*4], bh[nt2*4+1], bh[nt2*4+2], bh[nt2*4+3], addr);
                }
                #pragma unroll
                for (int mt = 0; mt < 4; ++mt)
                    #pragma unroll
                    for (int nt = 0; nt < 4; ++nt)
                        mma_h(acc[w][mt][nt], &af[mt*4], &bh[(nt >> 1)*4 + (nt & 1)*2]);
            }
        }
    };

    issue(0);
    issue(1);
    for (int c = 0; c < NC; ++c) {
        if (c + 1 < NC) { cp_wait<1>(); } else { cp_wait<0>(); }
        __syncthreads();
        compute(c);
        if (c + 2 < NC) issue(c + 2);
    }

    const int gg = lane >> 2;
    const int q4 = lane & 3;
    #pragma unroll
    for (int w = 0; w < 2; ++w) {
        int nbase = n0 + w * 128 + wn * 32;
        #pragma unroll
        for (int mt = 0; mt < 4; ++mt) {
            #pragma unroll
            for (int half = 0; half < 2; ++half) {
                int grow = m0 + wm * 64 + mt * 16 + gg + half * 8;
                if (grow < g.Mtot) {
                    int b = grow / g.RB, r = grow % g.RB;
                    long long rowoff = (long long)b * g.sC + (long long)r * g.N + nbase;
                    #pragma unroll
                    for (int nt = 0; nt < 4; ++nt) {
                        int ncol = nt * 8 + q4 * 2;
                        float vx = acc[w][mt][nt][half*2+0];
                        float vy = acc[w][mt][nt][half*2+1];
                        if (HALF_OUT) {
                            __half* crow = (__half*)g.C + rowoff;
                            *(__half2*)&crow[ncol] = __floats2half2_rn(vx, vy);
                        } else {
                            float* crow = (float*)g.C + rowoff;
                            float2 v;
                            v.x = vx + (g.bias ? g.bias[nbase + ncol]     : 0.f);
                            v.y = vy + (g.bias ? g.bias[nbase + ncol + 1] : 0.f);
                            *(float2*)&crow[ncol] = v;
                        }
                    }
                }
            }
        }
    }
}

__global__ __launch_bounds__(256)
void gemm_one(GDesc g)
{
    gemm_core<false>(g, blockIdx.y * 128, blockIdx.x * 256);
}

__global__ __launch_bounds__(256)
void gemm_pack(GPack p)
{
    const int bx = blockIdx.x;
    int di = 0;
    #pragma unroll
    for (int i = 0; i < 7; ++i)
        if (bx >= p.start[i] && bx < p.start[i+1]) di = i;
    const int local = bx - p.start[di];
    gemm_core<true>(p.d[di], (local / 5) * 128, (local % 5) * 256);
}

// ---------------- Tensor-core attention (256-row Q tiles) --------------------
// attn_pair smem: Q 32K | K 26K | V 26K = 84KB  (2 CTAs/SM)
// attn_fused smem: Q 32K | Ke 10K | Ve 10K | Kb 26K | Vb 26K = 104KB (2 CTAs/SM)
#define PAIR_SMEM  86016u
#define FUSED_SMEM 106496u
#define AQH 0u
#define P_AK 32768u
#define P_AV 59392u
#define F_AKE 32768u
#define F_AVE 43008u
#define F_AKB 53248u
#define F_AVB 79872u

// Q: direct swizzled 16B copies (256 rows)
template <bool CHECK>
__device__ __forceinline__ void att_stage_q(char* smc, const __half* Qb,
                                            int Sq, int q0, int t)
{
    #pragma unroll
    for (int i = 0; i < 8; ++i) {
        int lin = t + i * 256;          // 0..2047
        int row = lin >> 3;             // 0..255
        int ch  = lin & 7;
        uint4 v = make_uint4(0u, 0u, 0u, 0u);
        if (!CHECK || q0 + row < Sq)
            v = *(const uint4*)&Qb[(long long)(q0 + row) * CDIM + ch * 8];
        uint32_t off = (uint32_t)row * 128u + (uint32_t)((ch ^ (row & 7)) * 16);
        *(uint4*)(smc + AQH + off) = v;
    }
}

__device__ __forceinline__ void att_stage_kv(char* smc, uint32_t koff_base,
                                             uint32_t voff_base,
                                             const __half* Kb, const __half* Vb,
                                             int Skv, int nkv, int t)
{
    for (int lin = t; lin < nkv * 8; lin += 256) {
        int row = lin >> 3;
        int ch  = lin & 7;
        uint4 kv = make_uint4(0u, 0u, 0u, 0u);
        uint4 vv = make_uint4(0u, 0u, 0u, 0u);
        if (row < Skv) {
            kv = *(const uint4*)&Kb[(long long)row * CDIM + ch * 8];
            vv = *(const uint4*)&Vb[(long long)row * CDIM + ch * 8];
        }
        uint32_t off = (uint32_t)row * 128u + (uint32_t)((ch ^ (row & 7)) * 16);
        *(uint4*)(smc + koff_base + off) = kv;
        *(uint4*)(smc + voff_base + off) = vv;
    }
}

template <int SKV>
__device__ __forceinline__ void att_phase(uint32_t sm_q, uint32_t sm_k, uint32_t sm_v,
                                          int lane, int qbase,
                                          float* mrow, float* lrow, float O[8][4])
{
    constexpr int NCH = (SKV + 63) / 64;
    #pragma unroll
    for (int c = 0; c < NCH; ++c) {
        const int REM = SKV - c * 64;
        const int NKT = REM >= 64 ? 4 : (REM + 15) / 16;

        float S[8][4];
        #pragma unroll
        for (int nt = 0; nt < 8; ++nt)
            #pragma unroll
            for (int e = 0; e < 4; ++e) S[nt][e] = 0.f;

        #pragma unroll
        for (int ks = 0; ks < 4; ++ks) {
            uint32_t qh[4], kh[4];
            int arow = qbase + (lane & 15);
            int ach  = 2 * ks + (lane >> 4);
            uint32_t aoff = (uint32_t)arow * 128u + (uint32_t)((ach ^ (arow & 7)) * 16);
            ldm4(qh[0], qh[1], qh[2], qh[3], sm_q + aoff);
            #pragma unroll
            for (int nt2 = 0; nt2 < 4; ++nt2) {
                if (nt2 < NKT) {
                    int brow = c * 64 + nt2 * 16 + ((lane >> 4) & 1) * 8 + (lane & 7);
                    int bch  = 2 * ks + ((lane >> 3) & 1);
                    uint32_t boff = (uint32_t)brow * 128u
                                  + (uint32_t)((bch ^ (brow & 7)) * 16);
                    ldm4(kh[0], kh[1], kh[2], kh[3], sm_k + boff);
                    #pragma unroll
                    for (int sub = 0; sub < 2; ++sub)
                        mma_h(S[nt2 * 2 + sub], qh, &kh[sub*2]);
                }
            }
        }

        #pragma unroll
        for (int nt = 0; nt < 8; ++nt) {
            int col0 = c * 64 + nt * 8 + 2 * (lane & 3);
            #pragma unroll
            for (int e = 0; e < 4; ++e) {
                int col = col0 + (e & 1);
                float v = S[nt][e] * ATTN_SCALE;
                S[nt][e] = (col < SKV) ? v : -1e30f;
            }
        }

        float mx[2] = {-1e30f, -1e30f};
        #pragma unroll
        for (int nt = 0; nt < 8; ++nt) {
            mx[0] = fmaxf(mx[0], fmaxf(S[nt][0], S[nt][1]));
            mx[1] = fmaxf(mx[1], fmaxf(S[nt][2], S[nt][3]));
        }
        #pragma unroll
        for (int off = 1; off <= 2; off <<= 1) {
            mx[0] = fmaxf(mx[0], __shfl_xor_sync(0xffffffffu, mx[0], off));
            mx[1] = fmaxf(mx[1], __shfl_xor_sync(0xffffffffu, mx[1], off));
        }
        float mnew0 = fmaxf(mrow[0], mx[0]);
        float mnew1 = fmaxf(mrow[1], mx[1]);
        float corr0 = __expf(mrow[0] - mnew0);
        float corr1 = __expf(mrow[1] - mnew1);

        float ls[2] = {0.f, 0.f};
        #pragma unroll
        for (int nt = 0; nt < 8; ++nt) {
            S[nt][0] = __expf(S[nt][0] - mnew0); ls[0] += S[nt][0];
            S[nt][1] = __expf(S[nt][1] - mnew0); ls[0] += S[nt][1];
            S[nt][2] = __expf(S[nt][2] - mnew1); ls[1] += S[nt][2];
            S[nt][3] = __expf(S[nt][3] - mnew1); ls[1] += S[nt][3];
        }
        #pragma unroll
        for (int off = 1; off <= 2; off <<= 1) {
            ls[0] += __shfl_xor_sync(0xffffffffu, ls[0], off);
            ls[1] += __shfl_xor_sync(0xffffffffu, ls[1], off);
        }
        lrow[0] = lrow[0] * corr0 + ls[0];
        lrow[1] = lrow[1] * corr1 + ls[1];
        mrow[0] = mnew0; mrow[1] = mnew1;
        #pragma unroll
        for (int nt = 0; nt < 8; ++nt) {
            O[nt][0] *= corr0; O[nt][1] *= corr0;
            O[nt][2] *= corr1; O[nt][3] *= corr1;
        }

        #pragma unroll
        for (int ks = 0; ks < 4; ++ks) {
            if (ks < NKT) {
                uint32_t aph[4];
                {
                    int T0 = 2 * ks, T1 = 2 * ks + 1;
                    aph[0] = pack_h(S[T0][0], S[T0][1]);
                    aph[1] = pack_h(S[T0][2], S[T0][3]);
                    aph[2] = pack_h(S[T1][0], S[T1][1]);
                    aph[3] = pack_h(S[T1][2], S[T1][3]);
                }
                int krow = c * 64 + ks * 16 + (lane & 15);
                #pragma unroll
                for (int nt2 = 0; nt2 < 4; ++nt2) {
                    int chunk = nt2 * 2 + ((lane >> 4) & 1);
                    uint32_t voff = (uint32_t)krow * 128u
                                  + (uint32_t)((chunk ^ (krow & 7)) * 16);
                    uint32_t vh[4];
                    ldm4t(vh[0], vh[1], vh[2], vh[3], sm_v + voff);
                    mma_h(O[nt2 * 2 + 0], aph, &vh[0]);
                    mma_h(O[nt2 * 2 + 1], aph, &vh[2]);
                }
            }
        }
    }
}

// attn2+attn3 merged: X += softmax(X Kc^T) Vc ; 256-row Q tile, 2 q-groups
__global__ __launch_bounds__(256, 2)
void attn_pair(__half* __restrict__ bk, __half* __restrict__ bv,
               const __half* __restrict__ ck, const __half* __restrict__ cv)
{
    extern __shared__ char smem[];
    char* smc = smem;
    const uint32_t sm = smem_u32(smem);

    const int t  = threadIdx.x;
    const int z  = blockIdx.z;
    const int b  = z >> 1;
    __half* Xg = (z & 1) ? bv : bk;
    const int h  = blockIdx.y;

    const __half* Qb = Xg + ((long long)b * NTOK) * CDIM + h * HD;
    const __half* Kb = ck + ((long long)b * NTOK) * CDIM + h * HD;
    const __half* Vb = cv + ((long long)b * NTOK) * CDIM + h * HD;
    __half*       Ob = Xg + ((long long)b * NTOK) * CDIM + h * HD;

    att_stage_q<true>(smc, Qb, NTOK, 0, t);
    att_stage_kv(smc, P_AK, P_AV, Kb, Vb, NTOK, 208, t);
    __syncthreads();

    const int lane = t & 31;
    const int wid  = t >> 5;

    #pragma unroll
    for (int qg = 0; qg < 2; ++qg) {
        const int qbase = qg * 128 + wid * 16;
        if (qbase >= NTOK) continue;

        float O[8][4];
        #pragma unroll
        for (int nt = 0; nt < 8; ++nt)
            #pragma unroll
            for (int e = 0; e < 4; ++e) O[nt][e] = 0.f;
        float mrow[2] = {-1e30f, -1e30f};
        float lrow[2] = {0.f, 0.f};

        att_phase<NTOK>(sm + AQH, sm + P_AK, sm + P_AV, lane, qbase, mrow, lrow, O);

        float inv0 = 1.f / lrow[0];
        float inv1 = 1.f / lrow[1];
        #pragma unroll
        for (int halfq = 0; halfq < 2; ++halfq) {
            int row = qbase + (lane >> 2) + halfq * 8;
            if (row < NTOK) {
                float inv = halfq ? inv1 : inv0;
                __half* op = Ob + (long long)row * CDIM;
                #pragma unroll
                for (int nt = 0; nt < 8; ++nt) {
                    int d = nt * 8 + 2 * (lane & 3);
                    __half2 old = *(__half2*)&op[d];
                    float ox = __half2float(__low2half(old))  + O[nt][halfq*2+0] * inv;
                    float oy = __half2float(__high2half(old)) + O[nt][halfq*2+1] * inv;
                    *(__half2*)&op[d] = __floats2half2_rn(ox, oy);
                }
            }
        }
    }
}

// fused main attention: 256-row Q tiles, 2 q-groups over shared staged KV
__global__ __launch_bounds__(256, 2)
void attn_fused(const __half* __restrict__ Qg, const __half* __restrict__ Kg,
                const __half* __restrict__ Vg, const __half* __restrict__ bKg,
                const __half* __restrict__ bVg, __half* __restrict__ Og)
{
    extern __shared__ char smem[];
    char* smc = smem;
    const uint32_t sm = smem_u32(smem);

    const int t  = threadIdx.x;
    const int b  = blockIdx.z;
    const int h  = blockIdx.y;
    const int q0 = blockIdx.x * 256;

    const __half* Qb  = Qg  + ((long long)b * QLEN)    * CDIM + h * HD;
    const __half* Kb  = Kg  + ((long long)b * EHS_LEN) * CDIM + h * HD;
    const __half* Vb  = Vg  + ((long long)b * EHS_LEN) * CDIM + h * HD;
    const __half* bKb = bKg + ((long long)b * NTOK)    * CDIM + h * HD;
    const __half* bVb = bVg + ((long long)b * NTOK)    * CDIM + h * HD;
    __half*       Ob  = Og  + ((long long)b * QLEN)    * CDIM + h * HD;

    att_stage_q<false>(smc, Qb + (long long)q0 * CDIM, QLEN, 0, t);
    att_stage_kv(smc, F_AKE, F_AVE, Kb,  Vb,  EHS_LEN, 80,  t);
    att_stage_kv(smc, F_AKB, F_AVB, bKb, bVb, NTOK,    208, t);
    __syncthreads();

    const int lane = t & 31;
    const int wid  = t >> 5;

    #pragma unroll
    for (int qg = 0; qg < 2; ++qg) {
        const int qbase = qg * 128 + wid * 16;

        float O[8][4];
        float mrow[2], lrow[2];
        #pragma unroll
        for (int nt = 0; nt < 8; ++nt)
            #pragma unroll
            for (int e = 0; e < 4; ++e) O[nt][e] = 0.f;
        mrow[0] = mrow[1] = -1e30f;
        lrow[0] = lrow[1] = 0.f;

        att_phase<EHS_LEN>(sm + AQH, sm + F_AKE, sm + F_AVE, lane, qbase, mrow, lrow, O);

        float Oacc[8][4];
        {
            float inv0 = 1.f / lrow[0];
            float inv1 = 1.f / lrow[1];
            #pragma unroll
            for (int nt = 0; nt < 8; ++nt) {
                Oacc[nt][0] = O[nt][0] * inv0;
                Oacc[nt][1] = O[nt][1] * inv0;
                Oacc[nt][2] = O[nt][2] * inv1;
                Oacc[nt][3] = O[nt][3] * inv1;
                O[nt][0] = O[nt][1] = O[nt][2] = O[nt][3] = 0.f;
            }
            mrow[0] = mrow[1] = -1e30f;
            lrow[0] = lrow[1] = 0.f;
        }

        att_phase<NTOK>(sm + AQH, sm + F_AKB, sm + F_AVB, lane, qbase, mrow, lrow, O);

        float inv0 = 1.f / lrow[0];
        float inv1 = 1.f / lrow[1];
        #pragma unroll
        for (int halfq = 0; halfq < 2; ++halfq) {
            int row = q0 + qbase + (lane >> 2) + halfq * 8;
            float inv = halfq ? inv1 : inv0;
            __half* op = Ob + (long long)row * CDIM;
            #pragma unroll
            for (int nt = 0; nt < 8; ++nt) {
                int d = nt * 8 + 2 * (lane & 3);
                float vx = Oacc[nt][halfq*2+0] + O[nt][halfq*2+0] * inv;
                float vy = Oacc[nt][halfq*2+1] + O[nt][halfq*2+1] * inv;
                *(__half2*)&op[d] = __floats2half2_rn(vx, vy);
            }
        }
    }
}

// ---------------- host orchestration ---------------------------------------
template <typename T>
static inline T* sym(const void* s) { void* p; cudaGetSymbolAddress(&p, s); return (T*)p; }

extern "C" void kernel_launch(void* const* d_in, const int* in_sizes, int n_in,
                              void* d_out, int out_size)
{
    const float* hidden = (const float*)d_in[0];
    const float* enc    = (const float*)d_in[1];
    const float* w_q    = (const float*)d_in[2];
    const float* w_k    = (const float*)d_in[3];
    const float* w_v    = (const float*)d_in[4];
    const float* w_kb   = (const float*)d_in[5];
    const float* w_vb   = (const float*)d_in[6];
    const float* w_kc   = (const float*)d_in[7];
    const float* w_vc   = (const float*)d_in[8];
    const float* w_out  = (const float*)d_in[9];
    const float* b_out  = (const float*)d_in[10];
    float* out = (float*)d_out;

    __half* pq  = sym<__half>(&h_q);
    __half* pk  = sym<__half>(&h_k);
    __half* pv  = sym<__half>(&h_v);
    __half* pbk = sym<__half>(&h_bk);
    __half* pbv = sym<__half>(&h_bv);
    __half* pck = sym<__half>(&h_ck);
    __half* pcv = sym<__half>(&h_cv);

    __half* hidh = sym<__half>(&a_hid);
    __half* ench = sym<__half>(&a_enc);
    __half* poh  = sym<__half>(&a_po);
    __half* wqh  = sym<__half>(&w_q_h);
    __half* wkh  = sym<__half>(&w_k_h);
    __half* wvh  = sym<__half>(&w_v_h);
    __half* wkbh = sym<__half>(&w_kb_h);
    __half* wvbh = sym<__half>(&w_vb_h);
    __half* wkch = sym<__half>(&w_kc_h);
    __half* wvch = sym<__half>(&w_vc_h);
    __half* woh  = sym<__half>(&w_o_h);

    const long long bsEnc = (long long)LLEN * CROSSD;
    const long long encN  = (long long)B_ * LLEN * CROSSD;
    const long long hidN  = (long long)B_ * QLEN * CDIM;
    const long long boxOff = (long long)EHS_LEN * CROSSD;
    const long long clsOff = (long long)(EHS_LEN + NTOK) * CROSSD;

    cudaFuncSetAttribute(gemm_one,  cudaFuncAttributeMaxDynamicSharedMemorySize, GEMM_SMEM);
    cudaFuncSetAttribute(gemm_pack, cudaFuncAttributeMaxDynamicSharedMemorySize, GEMM_SMEM);
    cudaFuncSetAttribute(attn_pair, cudaFuncAttributeMaxDynamicSharedMemorySize, PAIR_SMEM);
    cudaFuncSetAttribute(attn_fused, cudaFuncAttributeMaxDynamicSharedMemorySize, FUSED_SMEM);

    // 1: all fp32 -> fp16 conversions in one launch
    {
        CPack10 cp;
        cp.d[0] = { (const float4*)hidden, (__half2*)hidh, (int)(hidN / 4) };
        cp.d[1] = { (const float4*)enc,    (__half2*)ench, (int)(encN / 4) };
        cp.d[2] = { (const float4*)w_q,    (__half2*)wqh,  CDIM * CDIM / 4 };
        cp.d[3] = { (const float4*)w_k,    (__half2*)wkh,  CDIM * CROSSD / 4 };
        cp.d[4] = { (const float4*)w_v,    (__half2*)wvh,  CDIM * CROSSD / 4 };
        cp.d[5] = { (const float4*)w_kb,   (__half2*)wkbh, CDIM * CROSSD / 4 };
        cp.d[6] = { (const float4*)w_vb,   (__half2*)wvbh, CDIM * CROSSD / 4 };
        cp.d[7] = { (const float4*)w_kc,   (__half2*)wkch, CDIM * CROSSD / 4 };
        cp.d[8] = { (const float4*)w_vc,   (__half2*)wvch, CDIM * CROSSD / 4 };
        cp.d[9] = { (const float4*)w_out,  (__half2*)woh,  CDIM * CDIM / 4 };
        dim3 grid(2048, 1, 10);
        cvt_multi10<<<grid, 256>>>(cp);
    }

    // 2: packed 7-way GEMM (128x256 tiles, fp16 outputs)
    {
        GPack p;
        const long long sEk = (long long)EHS_LEN*CDIM;
        const long long sNk = (long long)NTOK*CDIM;
        p.d[0] = { hidh,          wqh,  nullptr, pq,  B_*QLEN,    B_*QLEN, 0,     0,   CDIM, CDIM   };
        p.d[1] = { ench,          wkh,  nullptr, pk,  B_*EHS_LEN, EHS_LEN, bsEnc, sEk, CDIM, CROSSD };
        p.d[2] = { ench,          wvh,  nullptr, pv,  B_*EHS_LEN, EHS_LEN, bsEnc, sEk, CDIM, CROSSD };
        p.d[3] = { ench + boxOff, wkbh, nullptr, pbk, B_*NTOK,    NTOK,    bsEnc, sNk, CDIM, CROSSD };
        p.d[4] = { ench + boxOff, wvbh, nullptr, pbv, B_*NTOK,    NTOK,    bsEnc, sNk, CDIM, CROSSD };
        p.d[5] = { ench + clsOff, wkch, nullptr, pck, B_*NTOK,    NTOK,    bsEnc, sNk, CDIM, CROSSD };
        p.d[6] = { ench + clsOff, wvch, nullptr, pcv, B_*NTOK,    NTOK,    bsEnc, sNk, CDIM, CROSSD };
        int acc = 0;
        for (int i = 0; i < 7; ++i) {
            p.start[i] = acc;
            int mt = (p.d[i].Mtot + 127) / 128;
            acc += mt * 5;
        }
        p.start[7] = acc;
        gemm_pack<<<acc, 256, GEMM_SMEM>>>(p);
    }

    // 3: merged cls attention updates (256-row q-tile; one x-tile)
    {
        dim3 grid(1, HEADS, 2 * B_);
        attn_pair<<<grid, 256, PAIR_SMEM>>>(pbk, pbv, pck, pcv);
    }

    // 4: fused main + box attention -> fp16 a_po (256-row q-tiles)
    {
        dim3 grid(QLEN / 256, HEADS, B_);
        attn_fused<<<grid, 256, FUSED_SMEM>>>(pq, pk, pv, pbk, pbv, poh);
    }

    // 5: out-projection (fp32 + bias) into d_out
    {
        GDesc g = { poh, woh, b_out, out, B_*QLEN, B_*QLEN, 0, 0, CDIM, CDIM };
        dim3 grid(CDIM / 256, (B_*QLEN + 127) / 128, 1);
        gemm_one<<<grid, 256, GEMM_SMEM>>>(g);
    }
}